// round 3
// baseline (speedup 1.0000x reference)
#include <cuda_runtime.h>

// QuantumFeatureExtractor — analytic collapse, vectorized fp32 fast path.
//
// out[b,i] = cos(x[b,i] + theta[i]); 320 outputs.
// Round-2 post-mortem: kernel dur (4.2us) is ~90% fixed launch overhead.
// This round trims the executed-work slice: 80 threads, float4 load/store,
// 4x MUFU.COS per thread, 3-warp block for a minimal issue/retire tail.

#define BATCH 16
#define N_QUBITS 20
#define TOTAL (BATCH * N_QUBITS)   // 320
#define NTHREADS (TOTAL / 4)       // 80

__global__ __launch_bounds__(NTHREADS, 1)
void qfe_kernel(const float4* __restrict__ x4,
                const float* __restrict__ theta,
                float4* __restrict__ out4) {
    int t = threadIdx.x;           // 0..79
    float4 v = __ldg(&x4[t]);
    int base = t * 4;
    int q0 = base % N_QUBITS;      // 4 | 20, so q0..q0+3 never wrap past 20? (q0 in {0,4,8,12,16})
    // q0 is a multiple of 4 in [0,16], so q0+3 <= 19: no wraparound.
    float4 r;
    r.x = __cosf(v.x + __ldg(&theta[q0 + 0]));
    r.y = __cosf(v.y + __ldg(&theta[q0 + 1]));
    r.z = __cosf(v.z + __ldg(&theta[q0 + 2]));
    r.w = __cosf(v.w + __ldg(&theta[q0 + 3]));
    out4[t] = r;
}

extern "C" void kernel_launch(void* const* d_in, const int* in_sizes, int n_in,
                              void* d_out, int out_size) {
    const float4* x4   = (const float4*)d_in[0];  // [16,20] fp32, 320 elems
    const float* theta = (const float*)d_in[1];   // [20] fp32
    float4* out4 = (float4*)d_out;                // [16,20] fp32
    qfe_kernel<<<1, NTHREADS>>>(x4, theta, out4);
}

// round 6
// speedup vs baseline: 1.0833x; 1.0833x over previous
#include <cuda_runtime.h>

// QuantumFeatureExtractor — analytic collapse, vectorized fp32 path.
//
// out[b,i] = cos(x[b,i] + theta[i]); 320 outputs. At the ~4us launch floor.
// R4/R5 container failures coincided with float4 loads of theta (d_in[1]);
// a pooled-suballocated 80-byte tensor may not be 16B-aligned, and a
// misaligned LDG.128 traps. Reverted theta to scalar loads (known-passing
// R3 pattern); x/out keep float4 (top-level 256B-aligned buffers).

#define BATCH 16
#define N_QUBITS 20
#define TOTAL (BATCH * N_QUBITS)   // 320
#define NTHREADS (TOTAL / 4)       // 80

__global__ __launch_bounds__(NTHREADS, 1)
void qfe_kernel(const float4* __restrict__ x4,
                const float* __restrict__ theta,
                float4* __restrict__ out4) {
    int t = threadIdx.x;           // 0..79
    float4 v = x4[t];
    // element base = 4t; q0 = (4t) % 20 is a multiple of 4 in [0,16],
    // so the 4 thetas for this thread are theta[q0..q0+3], no wraparound.
    int q0 = (t % (N_QUBITS / 4)) * 4;   // (t % 5) * 4
    float4 r;
    r.x = __cosf(v.x + theta[q0 + 0]);
    r.y = __cosf(v.y + theta[q0 + 1]);
    r.z = __cosf(v.z + theta[q0 + 2]);
    r.w = __cosf(v.w + theta[q0 + 3]);
    out4[t] = r;
}

extern "C" void kernel_launch(void* const* d_in, const int* in_sizes, int n_in,
                              void* d_out, int out_size) {
    const float4* x4   = (const float4*)d_in[0];  // [16,20] fp32, 320 elems
    const float* theta = (const float*)d_in[1];   // [20] fp32
    float4* out4 = (float4*)d_out;                // [16,20] fp32
    qfe_kernel<<<1, NTHREADS>>>(x4, theta, out4);
}